// round 11
// baseline (speedup 1.0000x reference)
#include <cuda_runtime.h>
#include <cuda_fp16.h>
#include <cstdint>

// jordon_combined_layer: out[b] = ob + sum_u sigmoid(x[b,:]@W[:,u] + bias[u] + state*state_W[u]) * oW[u]
// B = 2097152, D = U = 64, L = 1. Output fp32 [B,1].
//
// R11: R10 with the band-address bug fixed. R10 toggled the 16-row band via
// `a0 ^ (b<<11)`, but bit 11 of (smem_base + swizzled_offset) is not
// guaranteed zero (linker placement + carry), so band 1 read garbage
// (rel_err 0.64). Band offset is now an ADD (+2048), which is exact:
// pre-swizzle offset bit 11 is 0 and the swizzle mask occupies bits 4-6.
// The k-step XOR (bits 5-6) remains valid: xs is 128-aligned so base bits
// 0-6 are zero and base+SWZ carries nothing below bit 7.
//
// Design (from R10): full W fragment set persists in 64 regs/lane (zero B
// smem traffic in the loop); CTA-wide coalesced staging; L2 prefetch of
// tile t+1; streaming hints; bands sequential (af = 16 regs).

#define ITERS        4
#define TILE_ROWS    128
#define ROWS_PER_CTA (ITERS * TILE_ROWS)   // 512

#define SWZ(o) ((o) ^ (((o) >> 3) & 0x70))

#define MMA16816(c0, c1, c2, c3, a0, a1, a2, a3, b0, b1)                         \
    asm volatile(                                                                \
        "mma.sync.aligned.m16n8k16.row.col.f32.f16.f16.f32 "                     \
        "{%0,%1,%2,%3}, {%4,%5,%6,%7}, {%8,%9}, {%0,%1,%2,%3};"                  \
        : "+f"(c0), "+f"(c1), "+f"(c2), "+f"(c3)                                 \
        : "r"(a0), "r"(a1), "r"(a2), "r"(a3), "r"(b0), "r"(b1))

#define LDMATRIX_X4(r0, r1, r2, r3, addr)                                        \
    asm volatile("ldmatrix.sync.aligned.m8n8.x4.shared.b16 {%0,%1,%2,%3}, [%4];" \
                 : "=r"(r0), "=r"(r1), "=r"(r2), "=r"(r3) : "r"(addr))

static __device__ __forceinline__ uint32_t h2bits(__half2 h) {
    return *reinterpret_cast<uint32_t*>(&h);
}

static __device__ __forceinline__ uint32_t smem_u32(const void* p) {
    return (uint32_t)__cvta_generic_to_shared(p);
}

__global__ void __launch_bounds__(128, 5)
jordon_kernel(const float* __restrict__ x,
              const float* __restrict__ state,
              const float* __restrict__ inW,
              const float* __restrict__ stW,
              const float* __restrict__ bias,
              const float* __restrict__ outW,
              const float* __restrict__ outb,
              float* __restrict__ out) {
    // x tile as fp16, SW128 swizzled: 128 rows x 64 halfs (128 B/row) = 16 KB
    __shared__ __align__(128) char xs[TILE_ROWS * 128];
    // W fragment staging (read once into registers after the prologue sync)
    __shared__ uint2  btab[4][8][32];
    // per-(n-tile, tg) constants: {0.5*(b+s)_u0, 0.5*oW_u0, 0.5*(b+s)_u1, 0.5*oW_u1}
    __shared__ float4 cwv[32];
    __shared__ float  ob;

    const int tid  = threadIdx.x;
    const int wid  = tid >> 5;
    const int lane = tid & 31;
    const int tg   = lane & 3;            // thread-in-group (col pair)
    const int g    = lane >> 2;           // fragment row within 8

    // ---- prologue: per-u constants ----
    if (tid < 32) {
        int j  = tid >> 2;
        int t4 = tid & 3;
        int u0 = j * 8 + t4 * 2;
        float s  = state[0];
        float s0 = s * stW[u0];
        float s1 = s * stW[u0 + 1];
        cwv[tid] = make_float4(0.5f * (bias[u0] + s0),     0.5f * outW[u0],
                               0.5f * (bias[u0 + 1] + s1), 0.5f * outW[u0 + 1]);
    }
    if (tid == 32) ob = outb[0];

    // ---- prologue: W fragment table, warp w builds k-step w (parallel) ----
    {
        const int k = wid;
        const int r = k * 16 + tg * 2;     // K index
#pragma unroll
        for (int j = 0; j < 8; j++) {
            int c = j * 8 + g;             // N index (u)
            __half2 lo = __floats2half2_rn(inW[(r    ) * 64 + c], inW[(r + 1) * 64 + c]);
            __half2 hi = __floats2half2_rn(inW[(r + 8) * 64 + c], inW[(r + 9) * 64 + c]);
            btab[k][j][lane] = make_uint2(h2bits(lo), h2bits(hi));
        }
    }
    __syncthreads();

    // ---- persist full W fragment set in registers (64 regs/lane) ----
    uint2 bb[4][8];
#pragma unroll
    for (int k = 0; k < 4; k++)
#pragma unroll
        for (int j = 0; j < 8; j++)
            bb[k][j] = btab[k][j][lane];

    const float4* xbase = reinterpret_cast<const float4*>(
        x + (size_t)blockIdx.x * ROWS_PER_CTA * 64);

    // ldmatrix base: this warp's band 0, k=0.
    // k toggles bits 5-6 via XOR (valid: xs 128-aligned -> a0 bits 5-6 come
    // only from the swizzle mask; XOR composes). Band advance is an ADD.
    const int lr  = lane & 15;
    const int lcb = (lane >> 4) * 16;      // 0 or 16
    const uint32_t a0 = smem_u32(xs) +
        (uint32_t)(SWZ(lr * 128 + lcb) + wid * 4096);   // wid*32 rows

#pragma unroll 1
    for (int it = 0; it < ITERS; it++) {
        // ---- stage tile: coalesced LDG.128 (512 B contiguous per warp), cvt, STS.64 ----
        const float4* src = xbase + (size_t)it * (TILE_ROWS * 16);
#pragma unroll
        for (int t = 0; t < 16; t++) {
            int i  = tid + t * 128;        // 2048 float4 per tile
            int r  = i >> 4;
            int c4 = i & 15;
            float4 v = __ldcs(&src[i]);
            uint2 hh;
            hh.x = h2bits(__floats2half2_rn(v.x, v.y));
            hh.y = h2bits(__floats2half2_rn(v.z, v.w));
            *reinterpret_cast<uint2*>(xs + SWZ(r * 128 + c4 * 8)) = hh;
        }

        // ---- prefetch tile t+1 into L2 while tile t computes (no regs/smem) ----
        if (it + 1 < ITERS) {
            const char* pf = reinterpret_cast<const char*>(
                xbase + (size_t)(it + 1) * (TILE_ROWS * 16));
            asm volatile("prefetch.global.L2 [%0];" :: "l"(pf + tid * 256));
            asm volatile("prefetch.global.L2 [%0];" :: "l"(pf + tid * 256 + 128));
        }
        __syncthreads();

        // ---- two 16-row bands, sequential; B entirely from registers ----
#pragma unroll
        for (int b = 0; b < 2; b++) {
            const uint32_t ab = a0 + (uint32_t)(b << 11);   // +16 rows (ADD, not XOR)
            uint32_t af[4][4];
#pragma unroll
            for (int k = 0; k < 4; k++)
                LDMATRIX_X4(af[k][0], af[k][1], af[k][2], af[k][3],
                            ab ^ (uint32_t)(k << 5));

            float p0 = 0.f, p1 = 0.f;
#pragma unroll
            for (int j = 0; j < 8; j++) {
                float c0 = 0.f, c1 = 0.f, c2 = 0.f, c3 = 0.f;
                MMA16816(c0, c1, c2, c3, af[0][0], af[0][1], af[0][2], af[0][3], bb[0][j].x, bb[0][j].y);
                MMA16816(c0, c1, c2, c3, af[1][0], af[1][1], af[1][2], af[1][3], bb[1][j].x, bb[1][j].y);
                MMA16816(c0, c1, c2, c3, af[2][0], af[2][1], af[2][2], af[2][3], bb[2][j].x, bb[2][j].y);
                MMA16816(c0, c1, c2, c3, af[3][0], af[3][1], af[3][2], af[3][3], bb[3][j].x, bb[3][j].y);

                // sigmoid(z)*oW = fma(tanh(z/2), oW/2, oW/2)
                float4 w = cwv[j * 4 + tg];
                float t, v;
                v = fmaf(c0, 0.5f, w.x);
                asm("tanh.approx.f32 %0, %1;" : "=f"(t) : "f"(v));
                p0 += fmaf(t, w.y, w.y);
                v = fmaf(c1, 0.5f, w.z);
                asm("tanh.approx.f32 %0, %1;" : "=f"(t) : "f"(v));
                p0 += fmaf(t, w.w, w.w);
                v = fmaf(c2, 0.5f, w.x);
                asm("tanh.approx.f32 %0, %1;" : "=f"(t) : "f"(v));
                p1 += fmaf(t, w.y, w.y);
                v = fmaf(c3, 0.5f, w.z);
                asm("tanh.approx.f32 %0, %1;" : "=f"(t) : "f"(v));
                p1 += fmaf(t, w.w, w.w);
            }

            // reduce across the 4 lanes sharing each row (tg dimension)
            p0 += __shfl_xor_sync(0xffffffffu, p0, 1);
            p0 += __shfl_xor_sync(0xffffffffu, p0, 2);
            p1 += __shfl_xor_sync(0xffffffffu, p1, 1);
            p1 += __shfl_xor_sync(0xffffffffu, p1, 2);

            if (tg == 0) {
                const size_t R = (size_t)blockIdx.x * ROWS_PER_CTA +
                                 it * TILE_ROWS + wid * 32 + b * 16;
                __stcs(&out[R + g],     p0 + ob);
                __stcs(&out[R + g + 8], p1 + ob);
            }
        }
        __syncthreads();   // xs reuse by next iteration's STS
    }
}

extern "C" void kernel_launch(void* const* d_in, const int* in_sizes, int n_in,
                              void* d_out, int out_size) {
    const float* x     = (const float*)d_in[0];  // [B, 64]
    const float* state = (const float*)d_in[1];  // [1, 1]
    const float* inW   = (const float*)d_in[2];  // [64, 64]
    const float* stW   = (const float*)d_in[3];  // [1, 1, 64]
    const float* bias  = (const float*)d_in[4];  // [1, 64]
    const float* outW  = (const float*)d_in[5];  // [64, 1]
    const float* outb  = (const float*)d_in[6];  // [1]
    float* out = (float*)d_out;                  // [B, 1]

    int grid = out_size / ROWS_PER_CTA;          // 2097152 / 512 = 4096
    jordon_kernel<<<grid, 128>>>(x, state, inW, stW, bias, outW, outb, out);
}

// round 12
// speedup vs baseline: 1.0356x; 1.0356x over previous
#include <cuda_runtime.h>
#include <cuda_fp16.h>
#include <cstdint>

// jordon_combined_layer: out[b] = ob + sum_u sigmoid(x[b,:]@W[:,u] + bias[u] + state*state_W[u]) * oW[u]
// B = 2097152, D = U = 64, L = 1. Output fp32 [B,1].
//
// R12: R9 (96.9us; best) + smem double-buffer software pipeline. R9 had two
// syncs/iter and zero loads in flight after each sync (single buffer); both
// DRAM (70%) and L1 (78.8%) sat below saturation. Now: one sync/iter,
// stage(t+1) issues its LDG burst BEFORE compute(t), L2 prefetch moves to
// t+2. Registers/occupancy unchanged (80 regs, 6 CTAs/SM, 34KB smem).
// W stays in the smem btab amortized over 2 bands/warp (register-persistent
// W regressed twice: R8, R11).

#define ITERS        4
#define TILE_ROWS    128
#define TILE_BYTES   (TILE_ROWS * 128)     // 16 KB per buffer
#define ROWS_PER_CTA (ITERS * TILE_ROWS)   // 512

#define SWZ(o) ((o) ^ (((o) >> 3) & 0x70))

#define MMA16816(c0, c1, c2, c3, a0, a1, a2, a3, b0, b1)                         \
    asm volatile(                                                                \
        "mma.sync.aligned.m16n8k16.row.col.f32.f16.f16.f32 "                     \
        "{%0,%1,%2,%3}, {%4,%5,%6,%7}, {%8,%9}, {%0,%1,%2,%3};"                  \
        : "+f"(c0), "+f"(c1), "+f"(c2), "+f"(c3)                                 \
        : "r"(a0), "r"(a1), "r"(a2), "r"(a3), "r"(b0), "r"(b1))

#define LDMATRIX_X4(r0, r1, r2, r3, addr)                                        \
    asm volatile("ldmatrix.sync.aligned.m8n8.x4.shared.b16 {%0,%1,%2,%3}, [%4];" \
                 : "=r"(r0), "=r"(r1), "=r"(r2), "=r"(r3) : "r"(addr))

static __device__ __forceinline__ uint32_t h2bits(__half2 h) {
    return *reinterpret_cast<uint32_t*>(&h);
}

static __device__ __forceinline__ uint32_t smem_u32(const void* p) {
    return (uint32_t)__cvta_generic_to_shared(p);
}

__global__ void __launch_bounds__(128, 6)
jordon_kernel(const float* __restrict__ x,
              const float* __restrict__ state,
              const float* __restrict__ inW,
              const float* __restrict__ stW,
              const float* __restrict__ bias,
              const float* __restrict__ outW,
              const float* __restrict__ outb,
              float* __restrict__ out) {
    // x tiles as fp16, SW128 swizzled, DOUBLE buffered: 2 x 128 rows x 128 B
    __shared__ __align__(128) char xs[2 * TILE_BYTES];
    // W fragment table: [k-step][n-tile][lane] -> {b0, b1} (half2 bit patterns)
    __shared__ uint2  btab[4][8][32];
    // per-(n-tile, tg) constants: {0.5*(b+s)_u0, 0.5*oW_u0, 0.5*(b+s)_u1, 0.5*oW_u1}
    __shared__ float4 cwv[32];
    __shared__ float  ob;

    const int tid  = threadIdx.x;
    const int wid  = tid >> 5;
    const int lane = tid & 31;
    const int tg   = lane & 3;            // thread-in-group (col pair)
    const int g    = lane >> 2;           // fragment row within 8

    // ---- prologue: per-u constants ----
    if (tid < 32) {
        int j  = tid >> 2;
        int t4 = tid & 3;
        int u0 = j * 8 + t4 * 2;
        float s  = state[0];
        float s0 = s * stW[u0];
        float s1 = s * stW[u0 + 1];
        cwv[tid] = make_float4(0.5f * (bias[u0] + s0),     0.5f * outW[u0],
                               0.5f * (bias[u0 + 1] + s1), 0.5f * outW[u0 + 1]);
    }
    if (tid == 32) ob = outb[0];

    // ---- prologue: W fragment table, warp w builds k-step w (parallel) ----
    {
        const int k = wid;
        const int r = k * 16 + tg * 2;     // K index
#pragma unroll
        for (int j = 0; j < 8; j++) {
            int c = j * 8 + g;             // N index (u)
            __half2 lo = __floats2half2_rn(inW[(r    ) * 64 + c], inW[(r + 1) * 64 + c]);
            __half2 hi = __floats2half2_rn(inW[(r + 8) * 64 + c], inW[(r + 9) * 64 + c]);
            btab[k][j][lane] = make_uint2(h2bits(lo), h2bits(hi));
        }
    }

    const float4* xbase = reinterpret_cast<const float4*>(
        x + (size_t)blockIdx.x * ROWS_PER_CTA * 64);

    // STS addresses: thread covers 16 float4 -> 16 uint2 slots per tile
    // ldmatrix addresses: per band b, k toggles bits 5-6 (XOR, swizzle-clean)
    const int lr  = lane & 15;
    const int lcb = (lane >> 4) * 16;      // 0 or 16
    uint32_t lm_addr[2][4];
#pragma unroll
    for (int b = 0; b < 2; b++)
#pragma unroll
        for (int k = 0; k < 4; k++)
            lm_addr[b][k] = smem_u32(xs) +
                (uint32_t)(SWZ((wid * 32 + b * 16 + lr) * 128 + k * 32 + lcb));

    // ---- stage tile 0 into buffer 0 ----
#pragma unroll
    for (int t = 0; t < 16; t++) {
        int i  = tid + t * 128;            // 2048 float4 per tile
        int r  = i >> 4;
        int c4 = i & 15;
        float4 v = __ldcs(&xbase[i]);
        uint2 hh;
        hh.x = h2bits(__floats2half2_rn(v.x, v.y));
        hh.y = h2bits(__floats2half2_rn(v.z, v.w));
        *reinterpret_cast<uint2*>(xs + SWZ(r * 128 + c4 * 8)) = hh;
    }
    // prefetch tile 1 into L2
    {
        const char* pf = reinterpret_cast<const char*>(xbase + TILE_ROWS * 16);
        asm volatile("prefetch.global.L2 [%0];" :: "l"(pf + tid * 256));
        asm volatile("prefetch.global.L2 [%0];" :: "l"(pf + tid * 256 + 128));
    }

#pragma unroll 1
    for (int it = 0; it < ITERS; it++) {
        __syncthreads();   // STS(tile it) visible; compute(it-1) done -> buf free

        // ---- stage tile it+1 into the other buffer (LDGs issue before compute) ----
        if (it + 1 < ITERS) {
            const float4* src = xbase + (size_t)(it + 1) * (TILE_ROWS * 16);
            char* dst = xs + ((it + 1) & 1) * TILE_BYTES;
#pragma unroll
            for (int t = 0; t < 16; t++) {
                int i  = tid + t * 128;
                int r  = i >> 4;
                int c4 = i & 15;
                float4 v = __ldcs(&src[i]);
                uint2 hh;
                hh.x = h2bits(__floats2half2_rn(v.x, v.y));
                hh.y = h2bits(__floats2half2_rn(v.z, v.w));
                *reinterpret_cast<uint2*>(dst + SWZ(r * 128 + c4 * 8)) = hh;
            }
            // prefetch tile it+2 into L2
            if (it + 2 < ITERS) {
                const char* pf = reinterpret_cast<const char*>(
                    xbase + (size_t)(it + 2) * (TILE_ROWS * 16));
                asm volatile("prefetch.global.L2 [%0];" :: "l"(pf + tid * 256));
                asm volatile("prefetch.global.L2 [%0];" :: "l"(pf + tid * 256 + 128));
            }
        }

        // ---- compute tile it from buffer it&1 ----
        const uint32_t bufoff = (uint32_t)((it & 1) * TILE_BYTES);

        uint32_t af[2][4][4];
#pragma unroll
        for (int b = 0; b < 2; b++)
#pragma unroll
            for (int k = 0; k < 4; k++)
                LDMATRIX_X4(af[b][k][0], af[b][k][1], af[b][k][2], af[b][k][3],
                            lm_addr[b][k] + bufoff);

        float p00 = 0.f, p01 = 0.f, p10 = 0.f, p11 = 0.f;
#pragma unroll
        for (int j = 0; j < 8; j++) {
            uint2 bb0 = btab[0][j][lane];
            uint2 bb1 = btab[1][j][lane];
            uint2 bb2 = btab[2][j][lane];
            uint2 bb3 = btab[3][j][lane];
            float4 w = cwv[j * 4 + tg];

#pragma unroll
            for (int b = 0; b < 2; b++) {
                float c0 = 0.f, c1 = 0.f, c2 = 0.f, c3 = 0.f;
                MMA16816(c0, c1, c2, c3, af[b][0][0], af[b][0][1], af[b][0][2], af[b][0][3], bb0.x, bb0.y);
                MMA16816(c0, c1, c2, c3, af[b][1][0], af[b][1][1], af[b][1][2], af[b][1][3], bb1.x, bb1.y);
                MMA16816(c0, c1, c2, c3, af[b][2][0], af[b][2][1], af[b][2][2], af[b][2][3], bb2.x, bb2.y);
                MMA16816(c0, c1, c2, c3, af[b][3][0], af[b][3][1], af[b][3][2], af[b][3][3], bb3.x, bb3.y);

                // sigmoid(z)*oW = fma(tanh(z/2), oW/2, oW/2)
                float t, v;
                v = fmaf(c0, 0.5f, w.x);
                asm("tanh.approx.f32 %0, %1;" : "=f"(t) : "f"(v));
                float q0 = fmaf(t, w.y, w.y);
                v = fmaf(c1, 0.5f, w.z);
                asm("tanh.approx.f32 %0, %1;" : "=f"(t) : "f"(v));
                q0 += fmaf(t, w.w, w.w);
                v = fmaf(c2, 0.5f, w.x);
                asm("tanh.approx.f32 %0, %1;" : "=f"(t) : "f"(v));
                float q1 = fmaf(t, w.y, w.y);
                v = fmaf(c3, 0.5f, w.z);
                asm("tanh.approx.f32 %0, %1;" : "=f"(t) : "f"(v));
                q1 += fmaf(t, w.w, w.w);

                if (b == 0) { p00 += q0; p01 += q1; }
                else        { p10 += q0; p11 += q1; }
            }
        }

        // reduce across the 4 lanes sharing each row (tg dimension)
        p00 += __shfl_xor_sync(0xffffffffu, p00, 1);
        p00 += __shfl_xor_sync(0xffffffffu, p00, 2);
        p01 += __shfl_xor_sync(0xffffffffu, p01, 1);
        p01 += __shfl_xor_sync(0xffffffffu, p01, 2);
        p10 += __shfl_xor_sync(0xffffffffu, p10, 1);
        p10 += __shfl_xor_sync(0xffffffffu, p10, 2);
        p11 += __shfl_xor_sync(0xffffffffu, p11, 1);
        p11 += __shfl_xor_sync(0xffffffffu, p11, 2);

        const size_t R = (size_t)blockIdx.x * ROWS_PER_CTA + it * TILE_ROWS + wid * 32;
        if (tg == 0) {
            __stcs(&out[R + g],      p00 + ob);
            __stcs(&out[R + g + 8],  p01 + ob);
            __stcs(&out[R + g + 16], p10 + ob);
            __stcs(&out[R + g + 24], p11 + ob);
        }
    }
}

extern "C" void kernel_launch(void* const* d_in, const int* in_sizes, int n_in,
                              void* d_out, int out_size) {
    const float* x     = (const float*)d_in[0];  // [B, 64]
    const float* state = (const float*)d_in[1];  // [1, 1]
    const float* inW   = (const float*)d_in[2];  // [64, 64]
    const float* stW   = (const float*)d_in[3];  // [1, 1, 64]
    const float* bias  = (const float*)d_in[4];  // [1, 64]
    const float* outW  = (const float*)d_in[5];  // [64, 1]
    const float* outb  = (const float*)d_in[6];  // [1]
    float* out = (float*)d_out;                  // [B, 1]

    int grid = out_size / ROWS_PER_CTA;          // 2097152 / 512 = 4096
    jordon_kernel<<<grid, 128>>>(x, state, inW, stW, bias, outW, outb, out);
}

// round 13
// speedup vs baseline: 1.0359x; 1.0003x over previous
#include <cuda_runtime.h>
#include <cuda_fp16.h>
#include <cstdint>

// jordon_combined_layer: out[b] = ob + sum_u sigmoid(x[b,:]@W[:,u] + bias[u] + state*state_W[u]) * oW[u]
// B = 2097152, D = U = 64, L = 1. Output fp32 [B,1].
//
// R12: R9 (96.9us; best) + smem double-buffer software pipeline. R9 had two
// syncs/iter and zero loads in flight after each sync (single buffer); both
// DRAM (70%) and L1 (78.8%) sat below saturation. Now: one sync/iter,
// stage(t+1) issues its LDG burst BEFORE compute(t), L2 prefetch moves to
// t+2. Registers/occupancy unchanged (80 regs, 6 CTAs/SM, 34KB smem).
// W stays in the smem btab amortized over 2 bands/warp (register-persistent
// W regressed twice: R8, R11).

#define ITERS        4
#define TILE_ROWS    128
#define TILE_BYTES   (TILE_ROWS * 128)     // 16 KB per buffer
#define ROWS_PER_CTA (ITERS * TILE_ROWS)   // 512

#define SWZ(o) ((o) ^ (((o) >> 3) & 0x70))

#define MMA16816(c0, c1, c2, c3, a0, a1, a2, a3, b0, b1)                         \
    asm volatile(                                                                \
        "mma.sync.aligned.m16n8k16.row.col.f32.f16.f16.f32 "                     \
        "{%0,%1,%2,%3}, {%4,%5,%6,%7}, {%8,%9}, {%0,%1,%2,%3};"                  \
        : "+f"(c0), "+f"(c1), "+f"(c2), "+f"(c3)                                 \
        : "r"(a0), "r"(a1), "r"(a2), "r"(a3), "r"(b0), "r"(b1))

#define LDMATRIX_X4(r0, r1, r2, r3, addr)                                        \
    asm volatile("ldmatrix.sync.aligned.m8n8.x4.shared.b16 {%0,%1,%2,%3}, [%4];" \
                 : "=r"(r0), "=r"(r1), "=r"(r2), "=r"(r3) : "r"(addr))

static __device__ __forceinline__ uint32_t h2bits(__half2 h) {
    return *reinterpret_cast<uint32_t*>(&h);
}

static __device__ __forceinline__ uint32_t smem_u32(const void* p) {
    return (uint32_t)__cvta_generic_to_shared(p);
}

__global__ void __launch_bounds__(128, 6)
jordon_kernel(const float* __restrict__ x,
              const float* __restrict__ state,
              const float* __restrict__ inW,
              const float* __restrict__ stW,
              const float* __restrict__ bias,
              const float* __restrict__ outW,
              const float* __restrict__ outb,
              float* __restrict__ out) {
    // x tiles as fp16, SW128 swizzled, DOUBLE buffered: 2 x 128 rows x 128 B
    __shared__ __align__(128) char xs[2 * TILE_BYTES];
    // W fragment table: [k-step][n-tile][lane] -> {b0, b1} (half2 bit patterns)
    __shared__ uint2  btab[4][8][32];
    // per-(n-tile, tg) constants: {0.5*(b+s)_u0, 0.5*oW_u0, 0.5*(b+s)_u1, 0.5*oW_u1}
    __shared__ float4 cwv[32];
    __shared__ float  ob;

    const int tid  = threadIdx.x;
    const int wid  = tid >> 5;
    const int lane = tid & 31;
    const int tg   = lane & 3;            // thread-in-group (col pair)
    const int g    = lane >> 2;           // fragment row within 8

    // ---- prologue: per-u constants ----
    if (tid < 32) {
        int j  = tid >> 2;
        int t4 = tid & 3;
        int u0 = j * 8 + t4 * 2;
        float s  = state[0];
        float s0 = s * stW[u0];
        float s1 = s * stW[u0 + 1];
        cwv[tid] = make_float4(0.5f * (bias[u0] + s0),     0.5f * outW[u0],
                               0.5f * (bias[u0 + 1] + s1), 0.5f * outW[u0 + 1]);
    }
    if (tid == 32) ob = outb[0];

    // ---- prologue: W fragment table, warp w builds k-step w (parallel) ----
    {
        const int k = wid;
        const int r = k * 16 + tg * 2;     // K index
#pragma unroll
        for (int j = 0; j < 8; j++) {
            int c = j * 8 + g;             // N index (u)
            __half2 lo = __floats2half2_rn(inW[(r    ) * 64 + c], inW[(r + 1) * 64 + c]);
            __half2 hi = __floats2half2_rn(inW[(r + 8) * 64 + c], inW[(r + 9) * 64 + c]);
            btab[k][j][lane] = make_uint2(h2bits(lo), h2bits(hi));
        }
    }

    const float4* xbase = reinterpret_cast<const float4*>(
        x + (size_t)blockIdx.x * ROWS_PER_CTA * 64);

    // STS addresses: thread covers 16 float4 -> 16 uint2 slots per tile
    // ldmatrix addresses: per band b, k toggles bits 5-6 (XOR, swizzle-clean)
    const int lr  = lane & 15;
    const int lcb = (lane >> 4) * 16;      // 0 or 16
    uint32_t lm_addr[2][4];
#pragma unroll
    for (int b = 0; b < 2; b++)
#pragma unroll
        for (int k = 0; k < 4; k++)
            lm_addr[b][k] = smem_u32(xs) +
                (uint32_t)(SWZ((wid * 32 + b * 16 + lr) * 128 + k * 32 + lcb));

    // ---- stage tile 0 into buffer 0 ----
#pragma unroll
    for (int t = 0; t < 16; t++) {
        int i  = tid + t * 128;            // 2048 float4 per tile
        int r  = i >> 4;
        int c4 = i & 15;
        float4 v = __ldcs(&xbase[i]);
        uint2 hh;
        hh.x = h2bits(__floats2half2_rn(v.x, v.y));
        hh.y = h2bits(__floats2half2_rn(v.z, v.w));
        *reinterpret_cast<uint2*>(xs + SWZ(r * 128 + c4 * 8)) = hh;
    }
    // prefetch tile 1 into L2
    {
        const char* pf = reinterpret_cast<const char*>(xbase + TILE_ROWS * 16);
        asm volatile("prefetch.global.L2 [%0];" :: "l"(pf + tid * 256));
        asm volatile("prefetch.global.L2 [%0];" :: "l"(pf + tid * 256 + 128));
    }

#pragma unroll 1
    for (int it = 0; it < ITERS; it++) {
        __syncthreads();   // STS(tile it) visible; compute(it-1) done -> buf free

        // ---- stage tile it+1 into the other buffer (LDGs issue before compute) ----
        if (it + 1 < ITERS) {
            const float4* src = xbase + (size_t)(it + 1) * (TILE_ROWS * 16);
            char* dst = xs + ((it + 1) & 1) * TILE_BYTES;
#pragma unroll
            for (int t = 0; t < 16; t++) {
                int i  = tid + t * 128;
                int r  = i >> 4;
                int c4 = i & 15;
                float4 v = __ldcs(&src[i]);
                uint2 hh;
                hh.x = h2bits(__floats2half2_rn(v.x, v.y));
                hh.y = h2bits(__floats2half2_rn(v.z, v.w));
                *reinterpret_cast<uint2*>(dst + SWZ(r * 128 + c4 * 8)) = hh;
            }
            // prefetch tile it+2 into L2
            if (it + 2 < ITERS) {
                const char* pf = reinterpret_cast<const char*>(
                    xbase + (size_t)(it + 2) * (TILE_ROWS * 16));
                asm volatile("prefetch.global.L2 [%0];" :: "l"(pf + tid * 256));
                asm volatile("prefetch.global.L2 [%0];" :: "l"(pf + tid * 256 + 128));
            }
        }

        // ---- compute tile it from buffer it&1 ----
        const uint32_t bufoff = (uint32_t)((it & 1) * TILE_BYTES);

        uint32_t af[2][4][4];
#pragma unroll
        for (int b = 0; b < 2; b++)
#pragma unroll
            for (int k = 0; k < 4; k++)
                LDMATRIX_X4(af[b][k][0], af[b][k][1], af[b][k][2], af[b][k][3],
                            lm_addr[b][k] + bufoff);

        float p00 = 0.f, p01 = 0.f, p10 = 0.f, p11 = 0.f;
#pragma unroll
        for (int j = 0; j < 8; j++) {
            uint2 bb0 = btab[0][j][lane];
            uint2 bb1 = btab[1][j][lane];
            uint2 bb2 = btab[2][j][lane];
            uint2 bb3 = btab[3][j][lane];
            float4 w = cwv[j * 4 + tg];

#pragma unroll
            for (int b = 0; b < 2; b++) {
                float c0 = 0.f, c1 = 0.f, c2 = 0.f, c3 = 0.f;
                MMA16816(c0, c1, c2, c3, af[b][0][0], af[b][0][1], af[b][0][2], af[b][0][3], bb0.x, bb0.y);
                MMA16816(c0, c1, c2, c3, af[b][1][0], af[b][1][1], af[b][1][2], af[b][1][3], bb1.x, bb1.y);
                MMA16816(c0, c1, c2, c3, af[b][2][0], af[b][2][1], af[b][2][2], af[b][2][3], bb2.x, bb2.y);
                MMA16816(c0, c1, c2, c3, af[b][3][0], af[b][3][1], af[b][3][2], af[b][3][3], bb3.x, bb3.y);

                // sigmoid(z)*oW = fma(tanh(z/2), oW/2, oW/2)
                float t, v;
                v = fmaf(c0, 0.5f, w.x);
                asm("tanh.approx.f32 %0, %1;" : "=f"(t) : "f"(v));
                float q0 = fmaf(t, w.y, w.y);
                v = fmaf(c1, 0.5f, w.z);
                asm("tanh.approx.f32 %0, %1;" : "=f"(t) : "f"(v));
                q0 += fmaf(t, w.w, w.w);
                v = fmaf(c2, 0.5f, w.x);
                asm("tanh.approx.f32 %0, %1;" : "=f"(t) : "f"(v));
                float q1 = fmaf(t, w.y, w.y);
                v = fmaf(c3, 0.5f, w.z);
                asm("tanh.approx.f32 %0, %1;" : "=f"(t) : "f"(v));
                q1 += fmaf(t, w.w, w.w);

                if (b == 0) { p00 += q0; p01 += q1; }
                else        { p10 += q0; p11 += q1; }
            }
        }

        // reduce across the 4 lanes sharing each row (tg dimension)
        p00 += __shfl_xor_sync(0xffffffffu, p00, 1);
        p00 += __shfl_xor_sync(0xffffffffu, p00, 2);
        p01 += __shfl_xor_sync(0xffffffffu, p01, 1);
        p01 += __shfl_xor_sync(0xffffffffu, p01, 2);
        p10 += __shfl_xor_sync(0xffffffffu, p10, 1);
        p10 += __shfl_xor_sync(0xffffffffu, p10, 2);
        p11 += __shfl_xor_sync(0xffffffffu, p11, 1);
        p11 += __shfl_xor_sync(0xffffffffu, p11, 2);

        const size_t R = (size_t)blockIdx.x * ROWS_PER_CTA + it * TILE_ROWS + wid * 32;
        if (tg == 0) {
            __stcs(&out[R + g],      p00 + ob);
            __stcs(&out[R + g + 8],  p01 + ob);
            __stcs(&out[R + g + 16], p10 + ob);
            __stcs(&out[R + g + 24], p11 + ob);
        }
    }
}

extern "C" void kernel_launch(void* const* d_in, const int* in_sizes, int n_in,
                              void* d_out, int out_size) {
    const float* x     = (const float*)d_in[0];  // [B, 64]
    const float* state = (const float*)d_in[1];  // [1, 1]
    const float* inW   = (const float*)d_in[2];  // [64, 64]
    const float* stW   = (const float*)d_in[3];  // [1, 1, 64]
    const float* bias  = (const float*)d_in[4];  // [1, 64]
    const float* outW  = (const float*)d_in[5];  // [64, 1]
    const float* outb  = (const float*)d_in[6];  // [1]
    float* out = (float*)d_out;                  // [B, 1]

    int grid = out_size / ROWS_PER_CTA;          // 2097152 / 512 = 4096
    jordon_kernel<<<grid, 128>>>(x, state, inW, stW, bias, outW, outb, out);
}